// round 2
// baseline (speedup 1.0000x reference)
#include <cuda_runtime.h>

// Problem constants
#define BB 8
#define LL 2500
#define DD 512
#define CC 8921
#define LP 2560           // L padded to multiple of 128 for GEMM2 K-loop
#define NLT (LP / 128)    // 20 l-tiles

// Scratch (allocation-free rule: __device__ globals)
__device__ float g_P[(size_t)BB * CC * LP];      // exp(att), padded with zeros  (~731 MB)
__device__ float g_part[(size_t)BB * CC * NLT];  // per-(row, l-tile) partial sums (~5.7 MB)
__device__ float g_RS[BB * CC];                  // row sums

// ---------------------------------------------------------------------------
// FMA-only exp: exp(x) = 2^(x*log2e), degree-6 poly of 2^f on [-0.5, 0.5].
// Avoids MUFU (rt=8/SMSP would cost ~1.5 ms for 178M exps).
// Logits here are bounded (|att| < ~4), so no max-subtraction is needed.
// ---------------------------------------------------------------------------
__device__ __forceinline__ float fexp(float x) {
    float t = fminf(fmaxf(x * 1.4426950408889634f, -126.0f), 126.0f);
    float n = rintf(t);
    float f = t - n;
    float p = 1.5435302423e-4f;
    p = fmaf(p, f, 1.3333558146e-3f);
    p = fmaf(p, f, 9.6181291076e-3f);
    p = fmaf(p, f, 5.5504108665e-2f);
    p = fmaf(p, f, 2.4022650696e-1f);
    p = fmaf(p, f, 6.9314718056e-1f);
    p = fmaf(p, f, 1.0f);
    return p * __int_as_float(((int)n + 127) << 23);
}

// ---------------------------------------------------------------------------
// GEMM1: att[b,c,l] = sum_d U[c,d] * x[b,l,d]   (both operands K-contiguous)
// Epilogue: P = exp(att) (0 in pad region), per-row partial sums per l-tile.
// Tile 128x128x16, 256 threads, 8x8 microtile, register-prefetch pipelining.
// ---------------------------------------------------------------------------
__global__ void __launch_bounds__(256, 2) gemm1_kernel(
    const float* __restrict__ X, const float* __restrict__ U)
{
    const int b  = blockIdx.z;
    const int m0 = blockIdx.y * 128;
    const int n0 = blockIdx.x * 128;
    const float* Bg = X + (size_t)b * LL * DD;

    __shared__ __align__(16) float As[16][128];
    __shared__ __align__(16) float Bs[16][128];

    const int tid = threadIdx.x;
    // Loader mapping: 128 rows x 16 k; thread -> (row = tid/2, 8 floats at (tid&1)*8)
    const int lr = tid >> 1;
    const int lc = (tid & 1) << 3;
    const int am = m0 + lr;
    const int bn = n0 + lr;
    const bool av = (am < CC);
    const bool bv = (bn < LL);
    const float* aPtr = U  + (size_t)am * DD + lc;
    const float* bPtr = Bg + (size_t)bn * DD + lc;

    const float4 z4 = make_float4(0.f, 0.f, 0.f, 0.f);
    float4 a0 = z4, a1 = z4, b0 = z4, b1 = z4;
    if (av) { a0 = *(const float4*)(aPtr); a1 = *(const float4*)(aPtr + 4); }
    if (bv) { b0 = *(const float4*)(bPtr); b1 = *(const float4*)(bPtr + 4); }

    const int tx = tid & 15;   // n dimension
    const int ty = tid >> 4;   // m dimension
    float acc[8][8] = {};

    #pragma unroll 1
    for (int kt = 0; kt < DD / 16; ++kt) {
        As[lc+0][lr] = a0.x; As[lc+1][lr] = a0.y; As[lc+2][lr] = a0.z; As[lc+3][lr] = a0.w;
        As[lc+4][lr] = a1.x; As[lc+5][lr] = a1.y; As[lc+6][lr] = a1.z; As[lc+7][lr] = a1.w;
        Bs[lc+0][lr] = b0.x; Bs[lc+1][lr] = b0.y; Bs[lc+2][lr] = b0.z; Bs[lc+3][lr] = b0.w;
        Bs[lc+4][lr] = b1.x; Bs[lc+5][lr] = b1.y; Bs[lc+6][lr] = b1.z; Bs[lc+7][lr] = b1.w;
        __syncthreads();
        if (kt + 1 < DD / 16) {
            const float* ap = aPtr + (kt + 1) * 16;
            const float* bp = bPtr + (kt + 1) * 16;
            if (av) { a0 = *(const float4*)(ap); a1 = *(const float4*)(ap + 4); }
            if (bv) { b0 = *(const float4*)(bp); b1 = *(const float4*)(bp + 4); }
        }
        #pragma unroll
        for (int k = 0; k < 16; ++k) {
            float4 av0 = *(const float4*)&As[k][ty * 8];
            float4 av1 = *(const float4*)&As[k][ty * 8 + 4];
            float4 bv0 = *(const float4*)&Bs[k][tx * 8];
            float4 bv1 = *(const float4*)&Bs[k][tx * 8 + 4];
            float ar[8] = {av0.x, av0.y, av0.z, av0.w, av1.x, av1.y, av1.z, av1.w};
            float br[8] = {bv0.x, bv0.y, bv0.z, bv0.w, bv1.x, bv1.y, bv1.z, bv1.w};
            #pragma unroll
            for (int i = 0; i < 8; ++i)
                #pragma unroll
                for (int j = 0; j < 8; ++j)
                    acc[i][j] = fmaf(ar[i], br[j], acc[i][j]);
        }
        __syncthreads();
    }

    // Epilogue: exp, store P (0 where l >= L), per-row partial sums (deterministic)
    float* Pout = g_P + (size_t)b * CC * LP;
    #pragma unroll
    for (int i = 0; i < 8; ++i) {
        const int gm = m0 + ty * 8 + i;
        float p[8];
        float s = 0.f;
        #pragma unroll
        for (int j = 0; j < 8; ++j) {
            const int gn = n0 + tx * 8 + j;
            p[j] = (gn < LL) ? fexp(acc[i][j]) : 0.f;
            s += p[j];
        }
        if (gm < CC) {
            float* o = Pout + (size_t)gm * LP + n0 + tx * 8;
            *(float4*)(o)     = make_float4(p[0], p[1], p[2], p[3]);
            *(float4*)(o + 4) = make_float4(p[4], p[5], p[6], p[7]);
        }
        // Reduce s over the 16 tx lanes (xor<=8 stays inside the 16-lane half-warp)
        s += __shfl_xor_sync(0xffffffffu, s, 1);
        s += __shfl_xor_sync(0xffffffffu, s, 2);
        s += __shfl_xor_sync(0xffffffffu, s, 4);
        s += __shfl_xor_sync(0xffffffffu, s, 8);
        if (tx == 0 && gm < CC)
            g_part[((size_t)b * CC + gm) * NLT + blockIdx.x] = s;
    }
}

// ---------------------------------------------------------------------------
// Deterministic row-sum reduction over the NLT partials
// ---------------------------------------------------------------------------
__global__ void rowsum_kernel() {
    const int i = blockIdx.x * blockDim.x + threadIdx.x;
    if (i < BB * CC) {
        float s = 0.f;
        #pragma unroll
        for (int t = 0; t < NLT; ++t) s += g_part[(size_t)i * NLT + t];
        g_RS[i] = s;
    }
}

// ---------------------------------------------------------------------------
// GEMM2: m[b,c,d] = (1/S[b,c]) * sum_l P[b,c,l] * x[b,l,d]
// A = P (K-contiguous, zero-padded to LP), B = x (N-contiguous).
// ---------------------------------------------------------------------------
__global__ void __launch_bounds__(256, 2) gemm2_kernel(
    const float* __restrict__ X, float* __restrict__ Out)
{
    const int b  = blockIdx.z;
    const int m0 = blockIdx.y * 128;
    const int n0 = blockIdx.x * 128;
    const float* Ag = g_P + (size_t)b * CC * LP;
    const float* Bg = X + (size_t)b * LL * DD;

    __shared__ __align__(16) float As[16][128];
    __shared__ __align__(16) float Bs[16][128];

    const int tid = threadIdx.x;
    // A loader: 128 rows x 16 k (transpose into As)
    const int alr = tid >> 1;
    const int alc = (tid & 1) << 3;
    const int am  = m0 + alr;
    const bool av = (am < CC);
    const float* aPtr = Ag + (size_t)am * LP + alc;
    // B loader: 16 k-rows x 128 n (direct)
    const int bkr = tid >> 4;          // 0..15
    const int bnc = (tid & 15) << 3;   // 0..120
    const float* bPtr = Bg + (size_t)bkr * DD + n0 + bnc;

    const float4 z4 = make_float4(0.f, 0.f, 0.f, 0.f);
    float4 a0 = z4, a1 = z4, b0 = z4, b1 = z4;
    if (av) { a0 = *(const float4*)(aPtr); a1 = *(const float4*)(aPtr + 4); }
    if (bkr < LL) { b0 = *(const float4*)(bPtr); b1 = *(const float4*)(bPtr + 4); }

    const int tx = tid & 15;
    const int ty = tid >> 4;
    float acc[8][8] = {};

    #pragma unroll 1
    for (int kt = 0; kt < LP / 16; ++kt) {
        As[alc+0][alr] = a0.x; As[alc+1][alr] = a0.y; As[alc+2][alr] = a0.z; As[alc+3][alr] = a0.w;
        As[alc+4][alr] = a1.x; As[alc+5][alr] = a1.y; As[alc+6][alr] = a1.z; As[alc+7][alr] = a1.w;
        *(float4*)&Bs[bkr][bnc]     = b0;
        *(float4*)&Bs[bkr][bnc + 4] = b1;
        __syncthreads();
        if (kt + 1 < LP / 16) {
            const float* ap = aPtr + (kt + 1) * 16;
            if (av) { a0 = *(const float4*)(ap); a1 = *(const float4*)(ap + 4); }
            const int gk = (kt + 1) * 16 + bkr;
            const float* bp = bPtr + (size_t)(kt + 1) * 16 * DD;
            if (gk < LL) { b0 = *(const float4*)(bp); b1 = *(const float4*)(bp + 4); }
            else         { b0 = z4; b1 = z4; }
        }
        #pragma unroll
        for (int k = 0; k < 16; ++k) {
            float4 av0 = *(const float4*)&As[k][ty * 8];
            float4 av1 = *(const float4*)&As[k][ty * 8 + 4];
            float4 bv0 = *(const float4*)&Bs[k][tx * 8];
            float4 bv1 = *(const float4*)&Bs[k][tx * 8 + 4];
            float ar[8] = {av0.x, av0.y, av0.z, av0.w, av1.x, av1.y, av1.z, av1.w};
            float br[8] = {bv0.x, bv0.y, bv0.z, bv0.w, bv1.x, bv1.y, bv1.z, bv1.w};
            #pragma unroll
            for (int i = 0; i < 8; ++i)
                #pragma unroll
                for (int j = 0; j < 8; ++j)
                    acc[i][j] = fmaf(ar[i], br[j], acc[i][j]);
        }
        __syncthreads();
    }

    #pragma unroll
    for (int i = 0; i < 8; ++i) {
        const int gm = m0 + ty * 8 + i;
        if (gm < CC) {
            const float inv = 1.0f / g_RS[b * CC + gm];
            float* o = Out + ((size_t)b * CC + gm) * DD + n0 + tx * 8;
            *(float4*)(o)     = make_float4(acc[i][0] * inv, acc[i][1] * inv,
                                            acc[i][2] * inv, acc[i][3] * inv);
            *(float4*)(o + 4) = make_float4(acc[i][4] * inv, acc[i][5] * inv,
                                            acc[i][6] * inv, acc[i][7] * inv);
        }
    }
}

// ---------------------------------------------------------------------------
extern "C" void kernel_launch(void* const* d_in, const int* in_sizes, int n_in,
                              void* d_out, int out_size)
{
    // x: [8,2500,512] = 10,240,000 elems; U: [8921,512] = 4,567,552 elems.
    const float* x;
    const float* U;
    if (in_sizes[0] == BB * LL * DD) { x = (const float*)d_in[0]; U = (const float*)d_in[1]; }
    else                             { x = (const float*)d_in[1]; U = (const float*)d_in[0]; }
    float* out = (float*)d_out;

    dim3 g1(NLT, (CC + 127) / 128, BB);                 // 20 x 70 x 8
    gemm1_kernel<<<g1, 256>>>(x, U);

    rowsum_kernel<<<(BB * CC + 255) / 256, 256>>>();

    dim3 g2(DD / 128, (CC + 127) / 128, BB);            // 4 x 70 x 8
    gemm2_kernel<<<g2, 256>>>(x, out);
}

// round 4
// speedup vs baseline: 1.0013x; 1.0013x over previous
#include <cuda_runtime.h>

// Problem constants
#define BB 8
#define LL 2500
#define DD 512
#define CC 8921
#define LP 2560           // L padded to multiple of 128 for GEMM2 K-loop
#define NLT (LP / 128)    // 20 l-tiles

// Scratch (allocation-free rule: __device__ globals)
__device__ float g_P[(size_t)BB * CC * LP];      // exp(att), padded with zeros  (~731 MB)
__device__ float g_part[(size_t)BB * CC * NLT];  // per-(row, l-tile) partial sums (~5.7 MB)
__device__ float g_RS[BB * CC];                  // row sums

// ---------------------------------------------------------------------------
// FMA-only exp: exp(x) = 2^(x*log2e), degree-6 poly of 2^f on [-0.5, 0.5].
// Avoids MUFU (rt=8/SMSP would cost ~1.5 ms for 178M exps).
// Logits here are bounded (|att| < ~4), so no max-subtraction is needed.
// ---------------------------------------------------------------------------
__device__ __forceinline__ float fexp(float x) {
    float t = fminf(fmaxf(x * 1.4426950408889634f, -126.0f), 126.0f);
    float n = rintf(t);
    float f = t - n;
    float p = 1.5435302423e-4f;
    p = fmaf(p, f, 1.3333558146e-3f);
    p = fmaf(p, f, 9.6181291076e-3f);
    p = fmaf(p, f, 5.5504108665e-2f);
    p = fmaf(p, f, 2.4022650696e-1f);
    p = fmaf(p, f, 6.9314718056e-1f);
    p = fmaf(p, f, 1.0f);
    return p * __int_as_float(((int)n + 127) << 23);
}

// ---------------------------------------------------------------------------
// GEMM1: att[b,c,l] = sum_d U[c,d] * x[b,l,d]   (both operands K-contiguous)
// Epilogue: P = exp(att) (0 in pad region), per-row partial sums per l-tile.
// Tile 128x128x16, 256 threads, 8x8 microtile, register-prefetch pipelining.
// ---------------------------------------------------------------------------
__global__ void __launch_bounds__(256, 2) gemm1_kernel(
    const float* __restrict__ X, const float* __restrict__ U)
{
    const int b  = blockIdx.z;
    const int m0 = blockIdx.y * 128;
    const int n0 = blockIdx.x * 128;
    const float* Bg = X + (size_t)b * LL * DD;

    __shared__ __align__(16) float As[16][128];
    __shared__ __align__(16) float Bs[16][128];

    const int tid = threadIdx.x;
    // Loader mapping: 128 rows x 16 k; thread -> (row = tid/2, 8 floats at (tid&1)*8)
    const int lr = tid >> 1;
    const int lc = (tid & 1) << 3;
    const int am = m0 + lr;
    const int bn = n0 + lr;
    const bool av = (am < CC);
    const bool bv = (bn < LL);
    const float* aPtr = U  + (size_t)am * DD + lc;
    const float* bPtr = Bg + (size_t)bn * DD + lc;

    const float4 z4 = make_float4(0.f, 0.f, 0.f, 0.f);
    float4 a0 = z4, a1 = z4, b0 = z4, b1 = z4;
    if (av) { a0 = *(const float4*)(aPtr); a1 = *(const float4*)(aPtr + 4); }
    if (bv) { b0 = *(const float4*)(bPtr); b1 = *(const float4*)(bPtr + 4); }

    const int tx = tid & 15;   // n dimension
    const int ty = tid >> 4;   // m dimension
    float acc[8][8] = {};

    #pragma unroll 1
    for (int kt = 0; kt < DD / 16; ++kt) {
        As[lc+0][lr] = a0.x; As[lc+1][lr] = a0.y; As[lc+2][lr] = a0.z; As[lc+3][lr] = a0.w;
        As[lc+4][lr] = a1.x; As[lc+5][lr] = a1.y; As[lc+6][lr] = a1.z; As[lc+7][lr] = a1.w;
        Bs[lc+0][lr] = b0.x; Bs[lc+1][lr] = b0.y; Bs[lc+2][lr] = b0.z; Bs[lc+3][lr] = b0.w;
        Bs[lc+4][lr] = b1.x; Bs[lc+5][lr] = b1.y; Bs[lc+6][lr] = b1.z; Bs[lc+7][lr] = b1.w;
        __syncthreads();
        if (kt + 1 < DD / 16) {
            const float* ap = aPtr + (kt + 1) * 16;
            const float* bp = bPtr + (kt + 1) * 16;
            if (av) { a0 = *(const float4*)(ap); a1 = *(const float4*)(ap + 4); }
            if (bv) { b0 = *(const float4*)(bp); b1 = *(const float4*)(bp + 4); }
        }
        #pragma unroll
        for (int k = 0; k < 16; ++k) {
            float4 av0 = *(const float4*)&As[k][ty * 8];
            float4 av1 = *(const float4*)&As[k][ty * 8 + 4];
            float4 bv0 = *(const float4*)&Bs[k][tx * 8];
            float4 bv1 = *(const float4*)&Bs[k][tx * 8 + 4];
            float ar[8] = {av0.x, av0.y, av0.z, av0.w, av1.x, av1.y, av1.z, av1.w};
            float br[8] = {bv0.x, bv0.y, bv0.z, bv0.w, bv1.x, bv1.y, bv1.z, bv1.w};
            #pragma unroll
            for (int i = 0; i < 8; ++i)
                #pragma unroll
                for (int j = 0; j < 8; ++j)
                    acc[i][j] = fmaf(ar[i], br[j], acc[i][j]);
        }
        __syncthreads();
    }

    // Epilogue: exp, store P (0 where l >= L), per-row partial sums (deterministic)
    float* Pout = g_P + (size_t)b * CC * LP;
    #pragma unroll
    for (int i = 0; i < 8; ++i) {
        const int gm = m0 + ty * 8 + i;
        float p[8];
        float s = 0.f;
        #pragma unroll
        for (int j = 0; j < 8; ++j) {
            const int gn = n0 + tx * 8 + j;
            p[j] = (gn < LL) ? fexp(acc[i][j]) : 0.f;
            s += p[j];
        }
        if (gm < CC) {
            float* o = Pout + (size_t)gm * LP + n0 + tx * 8;
            *(float4*)(o)     = make_float4(p[0], p[1], p[2], p[3]);
            *(float4*)(o + 4) = make_float4(p[4], p[5], p[6], p[7]);
        }
        // Reduce s over the 16 tx lanes (xor<=8 stays inside the 16-lane half-warp)
        s += __shfl_xor_sync(0xffffffffu, s, 1);
        s += __shfl_xor_sync(0xffffffffu, s, 2);
        s += __shfl_xor_sync(0xffffffffu, s, 4);
        s += __shfl_xor_sync(0xffffffffu, s, 8);
        if (tx == 0 && gm < CC)
            g_part[((size_t)b * CC + gm) * NLT + blockIdx.x] = s;
    }
}

// ---------------------------------------------------------------------------
// Deterministic row-sum reduction over the NLT partials
// ---------------------------------------------------------------------------
__global__ void rowsum_kernel() {
    const int i = blockIdx.x * blockDim.x + threadIdx.x;
    if (i < BB * CC) {
        float s = 0.f;
        #pragma unroll
        for (int t = 0; t < NLT; ++t) s += g_part[(size_t)i * NLT + t];
        g_RS[i] = s;
    }
}

// ---------------------------------------------------------------------------
// GEMM2: m[b,c,d] = (1/S[b,c]) * sum_l P[b,c,l] * x[b,l,d]
// A = P (K-contiguous, zero-padded to LP), B = x (N-contiguous).
// ---------------------------------------------------------------------------
__global__ void __launch_bounds__(256, 2) gemm2_kernel(
    const float* __restrict__ X, float* __restrict__ Out)
{
    const int b  = blockIdx.z;
    const int m0 = blockIdx.y * 128;
    const int n0 = blockIdx.x * 128;
    const float* Ag = g_P + (size_t)b * CC * LP;
    const float* Bg = X + (size_t)b * LL * DD;

    __shared__ __align__(16) float As[16][128];
    __shared__ __align__(16) float Bs[16][128];

    const int tid = threadIdx.x;
    // A loader: 128 rows x 16 k (transpose into As)
    const int alr = tid >> 1;
    const int alc = (tid & 1) << 3;
    const int am  = m0 + alr;
    const bool av = (am < CC);
    const float* aPtr = Ag + (size_t)am * LP + alc;
    // B loader: 16 k-rows x 128 n (direct)
    const int bkr = tid >> 4;          // 0..15
    const int bnc = (tid & 15) << 3;   // 0..120
    const float* bPtr = Bg + (size_t)bkr * DD + n0 + bnc;

    const float4 z4 = make_float4(0.f, 0.f, 0.f, 0.f);
    float4 a0 = z4, a1 = z4, b0 = z4, b1 = z4;
    if (av) { a0 = *(const float4*)(aPtr); a1 = *(const float4*)(aPtr + 4); }
    if (bkr < LL) { b0 = *(const float4*)(bPtr); b1 = *(const float4*)(bPtr + 4); }

    const int tx = tid & 15;
    const int ty = tid >> 4;
    float acc[8][8] = {};

    #pragma unroll 1
    for (int kt = 0; kt < LP / 16; ++kt) {
        As[alc+0][alr] = a0.x; As[alc+1][alr] = a0.y; As[alc+2][alr] = a0.z; As[alc+3][alr] = a0.w;
        As[alc+4][alr] = a1.x; As[alc+5][alr] = a1.y; As[alc+6][alr] = a1.z; As[alc+7][alr] = a1.w;
        *(float4*)&Bs[bkr][bnc]     = b0;
        *(float4*)&Bs[bkr][bnc + 4] = b1;
        __syncthreads();
        if (kt + 1 < LP / 16) {
            const float* ap = aPtr + (kt + 1) * 16;
            if (av) { a0 = *(const float4*)(ap); a1 = *(const float4*)(ap + 4); }
            const int gk = (kt + 1) * 16 + bkr;
            const float* bp = bPtr + (size_t)(kt + 1) * 16 * DD;
            if (gk < LL) { b0 = *(const float4*)(bp); b1 = *(const float4*)(bp + 4); }
            else         { b0 = z4; b1 = z4; }
        }
        #pragma unroll
        for (int k = 0; k < 16; ++k) {
            float4 av0 = *(const float4*)&As[k][ty * 8];
            float4 av1 = *(const float4*)&As[k][ty * 8 + 4];
            float4 bv0 = *(const float4*)&Bs[k][tx * 8];
            float4 bv1 = *(const float4*)&Bs[k][tx * 8 + 4];
            float ar[8] = {av0.x, av0.y, av0.z, av0.w, av1.x, av1.y, av1.z, av1.w};
            float br[8] = {bv0.x, bv0.y, bv0.z, bv0.w, bv1.x, bv1.y, bv1.z, bv1.w};
            #pragma unroll
            for (int i = 0; i < 8; ++i)
                #pragma unroll
                for (int j = 0; j < 8; ++j)
                    acc[i][j] = fmaf(ar[i], br[j], acc[i][j]);
        }
        __syncthreads();
    }

    #pragma unroll
    for (int i = 0; i < 8; ++i) {
        const int gm = m0 + ty * 8 + i;
        if (gm < CC) {
            const float inv = 1.0f / g_RS[b * CC + gm];
            float* o = Out + ((size_t)b * CC + gm) * DD + n0 + tx * 8;
            *(float4*)(o)     = make_float4(acc[i][0] * inv, acc[i][1] * inv,
                                            acc[i][2] * inv, acc[i][3] * inv);
            *(float4*)(o + 4) = make_float4(acc[i][4] * inv, acc[i][5] * inv,
                                            acc[i][6] * inv, acc[i][7] * inv);
        }
    }
}

// ---------------------------------------------------------------------------
extern "C" void kernel_launch(void* const* d_in, const int* in_sizes, int n_in,
                              void* d_out, int out_size)
{
    // x: [8,2500,512] = 10,240,000 elems; U: [8921,512] = 4,567,552 elems.
    const float* x;
    const float* U;
    if (in_sizes[0] == BB * LL * DD) { x = (const float*)d_in[0]; U = (const float*)d_in[1]; }
    else                             { x = (const float*)d_in[1]; U = (const float*)d_in[0]; }
    float* out = (float*)d_out;

    dim3 g1(NLT, (CC + 127) / 128, BB);                 // 20 x 70 x 8
    gemm1_kernel<<<g1, 256>>>(x, U);

    rowsum_kernel<<<(BB * CC + 255) / 256, 256>>>();

    dim3 g2(DD / 128, (CC + 127) / 128, BB);            // 4 x 70 x 8
    gemm2_kernel<<<g2, 256>>>(x, out);
}